// round 6
// baseline (speedup 1.0000x reference)
#include <cuda_runtime.h>
#include <cuda_fp16.h>

// ODECell: f = sigmoid(sigma*(in-mu)) = 0.5 + 0.5*tanh(0.5*sigma*(in-mu))
//   t = tanh(sH*x + cH)  with sH = 0.5*sigma (f16), cH = -0.5*sigma*mu (f16)
//   fA = baseA[u] + sum_d t * AH   (AH = 0.5*A, f32 accumulation)
//   fs = 64 + 0.5 * sum_d t
//   x <- 6 Euler steps of x*(1 - dt*(omega+fs)) + dt*fA
//
// R6: BB=4 — one weight LDG.128 feeds 4 batches (halves L1 wavefronts,
// quadruples per-warp independent chains), launch_bounds(128,4) = 128-reg
// budget for deep software pipelining. Grid 512.

#define UNITS 128
#define IDIM  128
#define DP    (IDIM / 2)     // 64 d-pairs
#define BATCH 2048
#define BB    4
#define OMEGA 0.1f
#define DT_U  (0.1f / 6.0f)

typedef unsigned int       u32;
typedef unsigned long long u64;

// Transposed packed weights [d_pair][u]: {sH2 bits, cH2 bits, AH0 bits, AH1 bits}
__device__ uint4 g_w[DP * UNITS];
__device__ float g_baseA[UNITS];

__device__ __forceinline__ u32 h2u(__half2 h) {
    u32 r; __builtin_memcpy(&r, &h, 4); return r;
}
__device__ __forceinline__ __half2 u2h(u32 u) {
    __half2 r; __builtin_memcpy(&r, &u, 4); return r;
}
__device__ __forceinline__ u32 tanh2u(u32 z) {
    u32 y; asm("tanh.approx.f16x2 %0, %1;" : "=r"(y) : "r"(z)); return y;
}
__device__ __forceinline__ u64 pack2(float lo, float hi) {
    u64 p;
    asm("mov.b64 %0, {%1, %2};" : "=l"(p)
        : "r"(__float_as_uint(lo)), "r"(__float_as_uint(hi)));
    return p;
}
__device__ __forceinline__ u64 fma2(u64 a, u64 b, u64 c) {
    u64 d; asm("fma.rn.f32x2 %0, %1, %2, %3;" : "=l"(d) : "l"(a), "l"(b), "l"(c));
    return d;
}
__device__ __forceinline__ u64 add2(u64 a, u64 b) {
    u64 d; asm("add.rn.f32x2 %0, %1, %2;" : "=l"(d) : "l"(a), "l"(b));
    return d;
}
__device__ __forceinline__ float2 unpack2(u64 p) {
    u32 lo, hi;
    asm("mov.b64 {%0, %1}, %2;" : "=r"(lo), "=r"(hi) : "l"(p));
    return make_float2(__uint_as_float(lo), __uint_as_float(hi));
}

// One block per unit u, 64 threads (one per d-pair): pack weights + reduce baseA.
__global__ void ode_prep_kernel(const float* __restrict__ A,
                                const float* __restrict__ sigma,
                                const float* __restrict__ mu) {
    const int u  = blockIdx.x;
    const int d2 = threadIdx.x;
    const int i  = u * IDIM + 2 * d2;

    float s0 = sigma[i],  s1 = sigma[i + 1];
    float m0 = mu[i],     m1 = mu[i + 1];
    float a0 = 0.5f * A[i], a1 = 0.5f * A[i + 1];

    __half2 sh2 = __halves2half2(__float2half_rn(0.5f * s0), __float2half_rn(0.5f * s1));
    __half2 ch2 = __halves2half2(__float2half_rn(-0.5f * s0 * m0),
                                 __float2half_rn(-0.5f * s1 * m1));

    uint4 w;
    w.x = h2u(sh2);
    w.y = h2u(ch2);
    w.z = __float_as_uint(a0);
    w.w = __float_as_uint(a1);
    g_w[d2 * UNITS + u] = w;

    __shared__ float red[2];
    float v = a0 + a1;
    #pragma unroll
    for (int off = 16; off > 0; off >>= 1)
        v += __shfl_down_sync(0xffffffffu, v, off);
    if ((d2 & 31) == 0) red[d2 >> 5] = v;
    __syncthreads();
    if (d2 == 0) g_baseA[u] = red[0] + red[1];
}

__global__ __launch_bounds__(UNITS, 4)   // 128-reg budget; grid-limited occupancy anyway
void ode_main_kernel(const float* __restrict__ inputs,
                     const float* __restrict__ state,
                     float* __restrict__ out) {
    const int u  = threadIdx.x;
    const int b0 = blockIdx.x * BB;

    // s_x[d2] = half2 x-pairs of batches b0..b0+3 at dims (2*d2, 2*d2+1)
    __shared__ uint4 s_x[DP];
    if (u < DP) {
        const float2* in2 = (const float2*)inputs;
        float2 xa = in2[((b0 + 0) * IDIM) / 2 + u];
        float2 xb = in2[((b0 + 1) * IDIM) / 2 + u];
        float2 xc = in2[((b0 + 2) * IDIM) / 2 + u];
        float2 xd = in2[((b0 + 3) * IDIM) / 2 + u];
        uint4 p;
        p.x = h2u(__halves2half2(__float2half_rn(xa.x), __float2half_rn(xa.y)));
        p.y = h2u(__halves2half2(__float2half_rn(xb.x), __float2half_rn(xb.y)));
        p.z = h2u(__halves2half2(__float2half_rn(xc.x), __float2half_rn(xc.y)));
        p.w = h2u(__halves2half2(__float2half_rn(xd.x), __float2half_rn(xd.y)));
        s_x[u] = p;
    }
    __syncthreads();

    u64 acc0 = 0, st0 = 0;   // packed f32x2 accumulators per batch
    u64 acc1 = 0, st1 = 0;
    u64 acc2 = 0, st2 = 0;
    u64 acc3 = 0, st3 = 0;

    const uint4* __restrict__ w = &g_w[u];

    #pragma unroll
    for (int d2 = 0; d2 < DP; ++d2) {
        uint4 wv = __ldg(&w[d2 * UNITS]);   // LDG.128: sH2, cH2, AH0, AH1
        uint4 xp = s_x[d2];                 // LDS.128 broadcast: 4 batches

        u64 a2 = pack2(__uint_as_float(wv.z), __uint_as_float(wv.w));
        __half2 sh2 = u2h(wv.x), ch2 = u2h(wv.y);

        {   // batch 0
            __half2 t = u2h(tanh2u(h2u(__hfma2(sh2, u2h(xp.x), ch2))));
            u64 tp = pack2(__low2float(t), __high2float(t));
            acc0 = fma2(tp, a2, acc0);
            st0  = add2(tp, st0);
        }
        {   // batch 1
            __half2 t = u2h(tanh2u(h2u(__hfma2(sh2, u2h(xp.y), ch2))));
            u64 tp = pack2(__low2float(t), __high2float(t));
            acc1 = fma2(tp, a2, acc1);
            st1  = add2(tp, st1);
        }
        {   // batch 2
            __half2 t = u2h(tanh2u(h2u(__hfma2(sh2, u2h(xp.z), ch2))));
            u64 tp = pack2(__low2float(t), __high2float(t));
            acc2 = fma2(tp, a2, acc2);
            st2  = add2(tp, st2);
        }
        {   // batch 3
            __half2 t = u2h(tanh2u(h2u(__hfma2(sh2, u2h(xp.w), ch2))));
            u64 tp = pack2(__low2float(t), __high2float(t));
            acc3 = fma2(tp, a2, acc3);
            st3  = add2(tp, st3);
        }
    }

    const float baseA = g_baseA[u];

    u64 accs[4] = {acc0, acc1, acc2, acc3};
    u64 sts[4]  = {st0, st1, st2, st3};

    #pragma unroll
    for (int k = 0; k < BB; ++k) {
        float2 a = unpack2(accs[k]), s = unpack2(sts[k]);
        float fA = baseA + a.x + a.y;
        float fs = (float)(IDIM / 2) + 0.5f * (s.x + s.y);
        float am = 1.0f - DT_U * (OMEGA + fs);
        float c  = DT_U * fA;
        float x  = state[(b0 + k) * UNITS + u];
        #pragma unroll
        for (int j = 0; j < 6; ++j) x = fmaf(x, am, c);
        out[(b0 + k) * UNITS + u] = x;
    }
}

extern "C" void kernel_launch(void* const* d_in, const int* in_sizes, int n_in,
                              void* d_out, int out_size) {
    const float* inputs = (const float*)d_in[0];
    const float* state  = (const float*)d_in[1];
    const float* A      = (const float*)d_in[2];
    const float* sigma  = (const float*)d_in[3];
    const float* mu     = (const float*)d_in[4];
    float* out = (float*)d_out;

    ode_prep_kernel<<<UNITS, DP>>>(A, sigma, mu);
    ode_main_kernel<<<BATCH / BB, UNITS>>>(inputs, state, out);
}